// round 17
// baseline (speedup 1.0000x reference)
#include <cuda_runtime.h>
#include <cuda_bf16.h>
#include <math.h>
#include <stdint.h>

// Problem constants
#define DDIM 1024
#define TDIM 2048
#define BDIM 32
#define MTOT 65536
#define WSTRIDE 2048        // W row stride in floats (2*D)

// GEMM tiling (bf16): 128x128 CTA tile, 8 warps of 32x64 warp tiles, 2 CTAs/SM
#define BM 128
#define BN 128
#define BK 64               // bf16 k-elements per stage
#define NTILES 8            // 1024 / BN
#define KT 16               // 1024 / BK
#define STAGES 3

#define STAGEB 18432u       // bytes per stage per matrix: 128 rows * 144B
#define SMEM_PART 110592u   // after 3*(A+B) stages
#define SMEM_TOTAL 111616u  // + partial[2][128] floats

// Scratch (static __device__ arrays: allocation-free)
__device__ __nv_bfloat16 g_encb[(size_t)MTOT * DDIM];
__device__ __nv_bfloat16 g_w2b[(size_t)DDIM * DDIM];
__device__ float g_qh[BDIM * DDIM];
__device__ float g_part[(size_t)NTILES * MTOT];

// ---------------------------------------------------------------------------
__device__ __forceinline__ void mma_bf16(float* d, const uint32_t* a, uint32_t b0, uint32_t b1) {
    asm volatile(
        "mma.sync.aligned.m16n8k16.row.col.f32.bf16.bf16.f32 "
        "{%0,%1,%2,%3}, {%4,%5,%6,%7}, {%8,%9}, {%0,%1,%2,%3};"
        : "+f"(d[0]), "+f"(d[1]), "+f"(d[2]), "+f"(d[3])
        : "r"(a[0]), "r"(a[1]), "r"(a[2]), "r"(a[3]), "r"(b0), "r"(b1));
}
__device__ __forceinline__ void cp16(uint32_t dst, const void* src) {
    asm volatile("cp.async.cg.shared.global [%0], [%1], 16;" :: "r"(dst), "l"(src));
}
#define LDSM4(r0, r1, r2, r3, addr) \
    asm volatile("ldmatrix.sync.aligned.m8n8.x4.shared.b16 {%0,%1,%2,%3}, [%4];" \
        : "=r"(r0), "=r"(r1), "=r"(r2), "=r"(r3) : "r"(addr))

__device__ __forceinline__ uint32_t smem_u32(const void* p) {
    uint32_t a;
    asm("{ .reg .u64 t; cvta.to.shared.u64 t, %1; cvt.u32.u64 %0, t; }" : "=r"(a) : "l"(p));
    return a;
}

// ---------------------------------------------------------------------------
// Convert enc (f32) -> g_encb (bf16). One float4 per thread.
__global__ __launch_bounds__(256) void conv_enc(const float4* __restrict__ src)
{
    const size_t i = (size_t)blockIdx.x * 256 + threadIdx.x;
    const float4 x = src[i];
    __nv_bfloat162 p0 = __floats2bfloat162_rn(x.x, x.y);
    __nv_bfloat162 p1 = __floats2bfloat162_rn(x.z, x.w);
    uint2 o;
    o.x = *(uint32_t*)&p0;
    o.y = *(uint32_t*)&p1;
    ((uint2*)g_encb)[i] = o;
}

// Convert W2 = W[:, 1024:2048] -> g_w2b (bf16).
__global__ __launch_bounds__(256) void conv_w2(const float* __restrict__ W)
{
    const int n = blockIdx.x;
    const int t = threadIdx.x;
    const float4 x = *(const float4*)(W + (size_t)n * WSTRIDE + DDIM + t * 4);
    __nv_bfloat162 p0 = __floats2bfloat162_rn(x.x, x.y);
    __nv_bfloat162 p1 = __floats2bfloat162_rn(x.z, x.w);
    uint2 o;
    o.x = *(uint32_t*)&p0;
    o.y = *(uint32_t*)&p1;
    ((uint2*)(g_w2b + (size_t)n * DDIM))[t] = o;
}

// ---------------------------------------------------------------------------
// qh[b,d] = W1[d,:] . hidden[b,:] + bias[d]
// W1 read ONCE (4MB, was 128MB): 64 blocks, thread (dl,kq) owns d = blk*16+dl
// and k-slice kq*64..+63; 32 independent batch accumulators (MLP); shfl-reduce
// over the 16 kq lanes (xor 1,2,4,8 stays within each 16-lane half).
__global__ __launch_bounds__(256) void qh_kernel(
    const float* __restrict__ hidden, const float* __restrict__ W,
    const float* __restrict__ bias)
{
    const int tid = threadIdx.x;
    const int dl  = tid >> 4;           // 0..15
    const int kq  = tid & 15;           // 0..15
    const int d   = blockIdx.x * 16 + dl;
    const int k0  = kq * 64;

    const float* wr = W + (size_t)d * WSTRIDE + k0;

    float acc[32];
    #pragma unroll
    for (int b = 0; b < 32; b++) acc[b] = 0.f;

    #pragma unroll 4
    for (int kc = 0; kc < 16; kc++) {
        const float4 w4 = __ldg((const float4*)(wr + kc * 4));
        #pragma unroll
        for (int b = 0; b < 32; b++) {
            const float4 h4 = __ldg((const float4*)(hidden + (size_t)b * DDIM + k0 + kc * 4));
            acc[b] += w4.x * h4.x + w4.y * h4.y + w4.z * h4.z + w4.w * h4.w;
        }
    }

    #pragma unroll
    for (int b = 0; b < 32; b++) {
        #pragma unroll
        for (int o = 8; o > 0; o >>= 1)
            acc[b] += __shfl_xor_sync(0xFFFFFFFFu, acc[b], o);
    }
    if (kq == 0) {
        const float bd = bias[d];
        #pragma unroll
        for (int b = 0; b < 32; b++)
            g_qh[(size_t)b * DDIM + d] = acc[b] + bd;
    }
}

// ---------------------------------------------------------------------------
// bf16 GEMM: 128x128 CTA tile, 256 threads (8 warps, 32x64 warp tiles),
// 2 CTAs/SM, 3-stage cp.async pipeline. Split-COMP rotation; fa reloaded
// BEFORE fb23 so fb23's issue stream covers fa's LDS latency into the next
// COMP03 (fa was previously last-loaded, first-consumed).
__global__ __launch_bounds__(256, 2) void bf_gemm(const float* __restrict__ v)
{
    extern __shared__ char smem[];
    const uint32_t uAs = smem_u32(smem);              // A stages
    const uint32_t uBs = uAs + STAGES * STAGEB;       // B stages

    const int tid  = threadIdx.x;
    const int lane = tid & 31;
    const int warp = tid >> 5;
    const int wm   = warp >> 1;     // 0..3 (M, 32 rows)
    const int wn   = warp & 1;      // 0..1 (N, 64 cols)
    const int gid  = lane >> 2;
    const int tig  = lane & 3;

    const int nx   = blockIdx.x;
    const int m0   = blockIdx.y * BM;
    const int n0   = nx * BN;
    const int bidx = m0 >> 11;

    float acc[2][8][4];
    #pragma unroll
    for (int i = 0; i < 2; i++)
        #pragma unroll
        for (int j = 0; j < 8; j++)
            #pragma unroll
            for (int k = 0; k < 4; k++) acc[i][j][k] = 0.f;

    // cp.async mapping (256 threads): A/B each 128 rows x 8 16B-chunks = 1024
    // ops -> rows {ra+32j} j=0..3, chunk c8.
    const int ra = tid >> 3;            // 0..31
    const int c8 = tid & 7;             // 0..7
    const uint32_t dA = uAs + (uint32_t)ra * 144 + (uint32_t)c8 * 16;
    const uint32_t dB = uBs + (uint32_t)ra * 144 + (uint32_t)c8 * 16;
    const __nv_bfloat16* pA = g_encb + (size_t)(m0 + ra) * DDIM + c8 * 8;
    const __nv_bfloat16* pB = g_w2b  + (size_t)(n0 + ra) * DDIM + c8 * 8;

    #define ISSUE_TILE(c, soff)                                                  \
    do {                                                                         \
        const __nv_bfloat16* _ga = pA + (size_t)(c) * BK;                        \
        const __nv_bfloat16* _gb = pB + (size_t)(c) * BK;                        \
        _Pragma("unroll")                                                        \
        for (int j = 0; j < 4; j++) {                                            \
            cp16(dA + (soff) + (uint32_t)j * 4608u, _ga + (size_t)j * 32 * DDIM);\
            cp16(dB + (soff) + (uint32_t)j * 4608u, _gb + (size_t)j * 32 * DDIM);\
        }                                                                        \
        asm volatile("cp.async.commit_group;");                                  \
    } while (0)

    // ldmatrix base addresses (lane-dependent)
    const uint32_t aBase = uAs + (uint32_t)(wm * 32 + (lane & 15)) * 144 + (uint32_t)(lane >> 4) * 16;
    const uint32_t bBase = uBs + (uint32_t)(wn * 64 + (lane & 15)) * 144 + (uint32_t)(lane >> 4) * 16;

    uint32_t fa[2][4];
    uint32_t fb[4][4];

    #define LDSM_FB01(off)                                                       \
    do {                                                                         \
        LDSM4(fb[0][0], fb[0][1], fb[0][2], fb[0][3], bBase + (off));            \
        LDSM4(fb[1][0], fb[1][1], fb[1][2], fb[1][3], bBase + (off) + 2304u);    \
    } while (0)
    #define LDSM_FB23(off)                                                       \
    do {                                                                         \
        LDSM4(fb[2][0], fb[2][1], fb[2][2], fb[2][3], bBase + (off) + 4608u);    \
        LDSM4(fb[3][0], fb[3][1], fb[3][2], fb[3][3], bBase + (off) + 6912u);    \
    } while (0)
    #define LDSM_FA(off)                                                         \
    do {                                                                         \
        LDSM4(fa[0][0], fa[0][1], fa[0][2], fa[0][3], aBase + (off));            \
        LDSM4(fa[1][0], fa[1][1], fa[1][2], fa[1][3], aBase + (off) + 2304u);    \
    } while (0)

    // COMP split: ni 0-3 uses fb[0..1], ni 4-7 uses fb[2..3]; both use fa.
    #define COMP03()                                                             \
    do {                                                                         \
        _Pragma("unroll")                                                        \
        for (int mi = 0; mi < 2; mi++)                                           \
            _Pragma("unroll")                                                    \
            for (int ni = 0; ni < 4; ni++)                                       \
                mma_bf16(acc[mi][ni], fa[mi],                                    \
                         fb[ni >> 1][ni & 1], fb[ni >> 1][2 + (ni & 1)]);        \
    } while (0)
    #define COMP47()                                                             \
    do {                                                                         \
        _Pragma("unroll")                                                        \
        for (int mi = 0; mi < 2; mi++)                                           \
            _Pragma("unroll")                                                    \
            for (int ni = 4; ni < 8; ni++)                                       \
                mma_bf16(acc[mi][ni], fa[mi],                                    \
                         fb[ni >> 1][ni & 1], fb[ni >> 1][2 + (ni & 1)]);        \
    } while (0)

    // Prologue: fill stages 0 and 1; stage 0 resident, load ks0 fragments.
    ISSUE_TILE(0, 0u);
    ISSUE_TILE(1, STAGEB);
    asm volatile("cp.async.wait_group 1;");
    __syncthreads();
    LDSM_FB01(0u); LDSM_FA(0u); LDSM_FB23(0u);

    uint32_t sOff   = 0u;                 // stage offset being consumed
    uint32_t issOff = 2u * STAGEB;        // stage offset for tile kt+2

    for (int kt = 0; kt < KT; kt++) {
        // ks0 (fragments already resident); reload for ks1 interleaved
        COMP03(); LDSM_FB01(sOff + 32u);
        if (kt + 2 < KT) ISSUE_TILE(kt + 2, issOff);
        COMP47(); LDSM_FA(sOff + 32u); LDSM_FB23(sOff + 32u);
        // ks1
        COMP03(); LDSM_FB01(sOff + 64u);
        COMP47(); LDSM_FA(sOff + 64u); LDSM_FB23(sOff + 64u);
        // ks2
        COMP03(); LDSM_FB01(sOff + 96u);
        COMP47(); LDSM_FA(sOff + 96u); LDSM_FB23(sOff + 96u);
        // ks3 (no reload within stage)
        COMP03(); COMP47();

        if (kt + 1 < KT) {
            if (kt + 2 < KT) asm volatile("cp.async.wait_group 1;");
            else             asm volatile("cp.async.wait_group 0;");
            __syncthreads();
            sOff   += STAGEB; if (sOff   == 3u * STAGEB) sOff   = 0u;
            issOff += STAGEB; if (issOff == 3u * STAGEB) issOff = 0u;
            LDSM_FB01(sOff); LDSM_FA(sOff); LDSM_FB23(sOff);
        }
    }

    // Epilogue: relu(acc + qh) * v, reduced over this CTA's 128 d-columns.
    float* partial = (float*)(smem + SMEM_PART);   // [2][128]
    float pr[2][2];
    #pragma unroll
    for (int mi = 0; mi < 2; mi++) { pr[mi][0] = 0.f; pr[mi][1] = 0.f; }

    #pragma unroll
    for (int ni = 0; ni < 8; ni++) {
        const int c = n0 + wn * 64 + ni * 8 + tig * 2;
        const float q0 = g_qh[(size_t)bidx * DDIM + c];
        const float q1 = g_qh[(size_t)bidx * DDIM + c + 1];
        const float v0 = v[c];
        const float v1 = v[c + 1];
        #pragma unroll
        for (int mi = 0; mi < 2; mi++) {
            pr[mi][0] += fmaxf(acc[mi][ni][0] + q0, 0.f) * v0;
            pr[mi][0] += fmaxf(acc[mi][ni][1] + q1, 0.f) * v1;
            pr[mi][1] += fmaxf(acc[mi][ni][2] + q0, 0.f) * v0;
            pr[mi][1] += fmaxf(acc[mi][ni][3] + q1, 0.f) * v1;
        }
    }

    __syncthreads();
    #pragma unroll
    for (int mi = 0; mi < 2; mi++)
        #pragma unroll
        for (int j = 0; j < 2; j++) {
            float p = pr[mi][j];
            p += __shfl_xor_sync(0xFFFFFFFFu, p, 1);
            p += __shfl_xor_sync(0xFFFFFFFFu, p, 2);
            if (tig == 0) partial[wn * BM + wm * 32 + mi * 16 + j * 8 + gid] = p;
        }
    __syncthreads();

    if (tid < BM) {
        const float s = partial[tid] + partial[BM + tid];
        g_part[(size_t)nx * MTOT + m0 + tid] = s;
    }
}

// ---------------------------------------------------------------------------
// Sum 8 N-strip partials -> scores, softmax over T. 1024 threads (2 t each).
__global__ __launch_bounds__(1024) void softmax_kernel(float* __restrict__ out)
{
    const int b = blockIdx.x;
    const int tid = threadIdx.x;
    __shared__ float red[1024];

    float vals[2];
    #pragma unroll
    for (int j = 0; j < 2; j++) {
        const int t = tid + j * 1024;
        float s = 0.f;
        #pragma unroll
        for (int nxi = 0; nxi < NTILES; nxi++)
            s += g_part[(size_t)nxi * MTOT + (size_t)b * TDIM + t];
        vals[j] = s;
    }
    float mx = fmaxf(vals[0], vals[1]);

    red[tid] = mx;
    __syncthreads();
    #pragma unroll
    for (int o = 512; o > 0; o >>= 1) {
        if (tid < o) red[tid] = fmaxf(red[tid], red[tid + o]);
        __syncthreads();
    }
    const float m = red[0];
    __syncthreads();

    float sum = 0.f;
    #pragma unroll
    for (int j = 0; j < 2; j++) {
        vals[j] = expf(vals[j] - m);
        sum += vals[j];
    }
    red[tid] = sum;
    __syncthreads();
    #pragma unroll
    for (int o = 512; o > 0; o >>= 1) {
        if (tid < o) red[tid] += red[tid + o];
        __syncthreads();
    }
    const float inv = 1.f / red[0];

    #pragma unroll
    for (int j = 0; j < 2; j++)
        out[(size_t)b * TDIM + tid + j * 1024] = vals[j] * inv;
}

// ---------------------------------------------------------------------------
extern "C" void kernel_launch(void* const* d_in, const int* in_sizes, int n_in,
                              void* d_out, int out_size)
{
    const float* hidden = (const float*)d_in[0];
    const float* enc    = (const float*)d_in[1];
    const float* W      = (const float*)d_in[2];
    const float* bias   = (const float*)d_in[3];
    const float* v      = (const float*)d_in[4];
    float* out = (float*)d_out;

    cudaFuncSetAttribute(bf_gemm, cudaFuncAttributeMaxDynamicSharedMemorySize, SMEM_TOTAL);

    conv_enc<<<65536, 256>>>((const float4*)enc);
    conv_w2<<<DDIM, 256>>>(W);
    qh_kernel<<<64, 256>>>(hidden, W, bias);
    bf_gemm<<<dim3(NTILES, MTOT / BM), 256, SMEM_TOTAL>>>(v);
    softmax_kernel<<<BDIM, 1024>>>(out);
}